// round 10
// baseline (speedup 1.0000x reference)
#include <cuda_runtime.h>
#include <math.h>
#include <stdint.h>

#define S_LEN    2048
#define D_MODEL  1024
#define N_HEADS  16
#define HEAD_DIM 64
#define BATCH    2
#define NTOK     (BATCH * S_LEN)   // 4096

// -------- scratch (device globals: no allocations allowed) --------
__device__ float g_Q[NTOK * D_MODEL];
__device__ float g_K[NTOK * D_MODEL];
__device__ float g_V[NTOK * D_MODEL];
__device__ float g_C[NTOK * D_MODEL];
__device__ float g_Xr[NTOK * D_MODEL];            // tf32-rounded x
__device__ float g_Wr[4][D_MODEL * D_MODEL];      // tf32-rounded Wq,Wk,Wv,Wo
__device__ float g_cos[S_LEN * 32];
__device__ float g_sin[S_LEN * 32];

#define LOG2E 1.4426950408889634f

__device__ __forceinline__ unsigned f2tf(float x) {
    unsigned u;
    asm("cvt.rna.tf32.f32 %0, %1;" : "=r"(u) : "f"(x));
    return u;
}
__device__ __forceinline__ float f2tff(float x) { return __uint_as_float(f2tf(x)); }

__device__ __forceinline__ void mma8(float c[4], const unsigned a[4],
                                     unsigned b0, unsigned b1) {
    asm volatile(
        "mma.sync.aligned.m16n8k8.row.col.f32.tf32.tf32.f32 "
        "{%0,%1,%2,%3},{%4,%5,%6,%7},{%8,%9},{%0,%1,%2,%3};"
        : "+f"(c[0]), "+f"(c[1]), "+f"(c[2]), "+f"(c[3])
        : "r"(a[0]), "r"(a[1]), "r"(a[2]), "r"(a[3]), "r"(b0), "r"(b1));
}

// =================================================================
// Pre-round x and the four weights to tf32-valued fp32 (one pass).
// =================================================================
__global__ void preround_kernel(const float* __restrict__ x,
                                const float* __restrict__ Wq,
                                const float* __restrict__ Wk,
                                const float* __restrict__ Wv,
                                const float* __restrict__ Wo)
{
    const int NX = NTOK * D_MODEL / 4;
    const int NW = D_MODEL * D_MODEL / 4;
    int i = blockIdx.x * blockDim.x + threadIdx.x;
    const float4* src;
    float4* dst;
    if (i < NX) { src = (const float4*)x; dst = (float4*)g_Xr; }
    else {
        int j = i - NX;
        int w = j / NW;
        i = j - w * NW;
        const float* ws[4] = {Wq, Wk, Wv, Wo};
        src = (const float4*)ws[w];
        dst = (float4*)g_Wr[w];
    }
    float4 v = src[i];
    v.x = f2tff(v.x); v.y = f2tff(v.y); v.z = f2tff(v.z); v.w = f2tff(v.w);
    dst[i] = v;
}

// =================================================================
// RoPE table (fp32 angle matching jnp, fp64 sincos)
// =================================================================
__global__ void rope_table_kernel()
{
    int i = blockIdx.x * blockDim.x + threadIdx.x;
    if (i >= S_LEN * 32) return;
    int pos = i >> 5;
    int f   = i & 31;
    float e    = (float)(2 * f) / 64.0f;
    float pw   = powf(10000.0f, e);
    float invf = 1.0f / pw;
    float angf = (float)pos * invf;
    double s, c;
    sincos((double)angf, &s, &c);
    g_cos[i] = (float)c;
    g_sin[i] = (float)s;
}

// =================================================================
// TF32 GEMM core: C[M,N] = A[M,K] @ B[N,K]^T, inputs pre-rounded.
// 128x128x16 CTA tile, 128 threads = 4 warps (2x2), 64x64 warp tile.
// 3-stage cp.async, ONE sync per iter.  (R8 known-good)
// =================================================================
#define AST 20

__device__ __forceinline__ void gemm_body(
    const float* __restrict__ A, const float* __restrict__ B,
    float* __restrict__ C, int M, int N, int K,
    int mb, int nb, int rope_mode, float scale, int round_out)
{
    __shared__ __align__(16) float As[3][128 * AST];
    __shared__ __align__(16) float Bs[3][128 * AST];

    const int t    = threadIdx.x;
    const int warp = t >> 5, lane = t & 31;
    const int g    = lane >> 2, tig = lane & 3;
    const int wm   = (warp >> 1) * 64;   // 2x2 warp grid
    const int wn   = (warp & 1) * 64;

    float acc[4][8][4];
#pragma unroll
    for (int mt = 0; mt < 4; mt++)
#pragma unroll
        for (int nt = 0; nt < 8; nt++)
#pragma unroll
            for (int i = 0; i < 4; i++) acc[mt][nt][i] = 0.f;

    const int lrow = t >> 2, lcol = (t & 3) * 4;   // lrow 0..31

#define LOAD_STAGE3(buf, kt)                                                       \
    do {                                                                           \
        _Pragma("unroll")                                                          \
        for (int rr = 0; rr < 4; rr++) {                                           \
            int row = lrow + rr * 32;                                              \
            unsigned da = (unsigned)__cvta_generic_to_shared(                      \
                &As[buf][row * AST + lcol]);                                       \
            const float* ga = A + (size_t)(mb + row) * K + (kt) + lcol;            \
            asm volatile("cp.async.cg.shared.global [%0], [%1], 16;"               \
                         :: "r"(da), "l"(ga));                                     \
            unsigned db = (unsigned)__cvta_generic_to_shared(                      \
                &Bs[buf][row * AST + lcol]);                                       \
            const float* gb = B + (size_t)(nb + row) * K + (kt) + lcol;            \
            asm volatile("cp.async.cg.shared.global [%0], [%1], 16;"               \
                         :: "r"(db), "l"(gb));                                     \
        }                                                                          \
        asm volatile("cp.async.commit_group;");                                    \
    } while (0)

    const int NIT = K / 16;
    LOAD_STAGE3(0, 0);
    LOAD_STAGE3(1, 16);

    for (int i = 0; i < NIT; i++) {
        asm volatile("cp.async.wait_group 1;");
        __syncthreads();
        if (i + 2 < NIT) {
            int nbuf = (i + 2) % 3;
            LOAD_STAGE3(nbuf, (i + 2) * 16);
        }
        const float* Ab = As[i % 3];
        const float* Bb = Bs[i % 3];

#pragma unroll
        for (int ks = 0; ks < 2; ks++) {
            const int kb = ks * 8;
            unsigned af[4][4], bf[8][2];
#pragma unroll
            for (int mt = 0; mt < 4; mt++) {
                int r0 = wm + mt * 16 + g;
                af[mt][0] = __float_as_uint(Ab[r0 * AST + kb + tig]);
                af[mt][1] = __float_as_uint(Ab[(r0 + 8) * AST + kb + tig]);
                af[mt][2] = __float_as_uint(Ab[r0 * AST + kb + tig + 4]);
                af[mt][3] = __float_as_uint(Ab[(r0 + 8) * AST + kb + tig + 4]);
            }
#pragma unroll
            for (int nt = 0; nt < 8; nt++) {
                int n0 = wn + nt * 8 + g;
                bf[nt][0] = __float_as_uint(Bb[n0 * AST + kb + tig]);
                bf[nt][1] = __float_as_uint(Bb[n0 * AST + kb + tig + 4]);
            }
#pragma unroll
            for (int mt = 0; mt < 4; mt++)
#pragma unroll
                for (int nt = 0; nt < 8; nt++)
                    mma8(acc[mt][nt], af[mt], bf[nt][0], bf[nt][1]);
        }
    }

    // ---- epilogue (optional fused RoPE, optional tf32 rounding) ----
#pragma unroll
    for (int mt = 0; mt < 4; mt++) {
#pragma unroll
        for (int nt = 0; nt < 8; nt++) {
            int row = mb + wm + mt * 16 + g;
            int col = nb + wn + nt * 8 + 2 * tig;
            float v0 = acc[mt][nt][0], v1 = acc[mt][nt][1];
            float v2 = acc[mt][nt][2], v3 = acc[mt][nt][3];
            if (rope_mode) {
                int fi = (col & 63) >> 1;
                int p0 = row & (S_LEN - 1);
                int p1 = (row + 8) & (S_LEN - 1);
                float c0 = g_cos[p0 * 32 + fi], s0 = g_sin[p0 * 32 + fi];
                float c1 = g_cos[p1 * 32 + fi], s1 = g_sin[p1 * 32 + fi];
                float r0 = v0 * c0 - v1 * s0, r1 = v0 * s0 + v1 * c0;
                float r2 = v2 * c1 - v3 * s1, r3 = v2 * s1 + v3 * c1;
                v0 = r0 * scale; v1 = r1 * scale;
                v2 = r2 * scale; v3 = r3 * scale;
            }
            if (round_out) {
                v0 = f2tff(v0); v1 = f2tff(v1);
                v2 = f2tff(v2); v3 = f2tff(v3);
            }
            *(float2*)&C[(size_t)row * N + col] = make_float2(v0, v1);
            *(float2*)&C[(size_t)(row + 8) * N + col] = make_float2(v2, v3);
        }
    }
}

__global__ __launch_bounds__(128, 2) void qkv_gemm_kernel(const float* __restrict__ A)
{
    const int z = blockIdx.z;
    float* outs[3] = {g_Q, g_K, g_V};
    const float* B = g_Wr[z];
    float* C = outs[z];
    int rope_mode = (z < 2) ? 1 : 0;
    float scale = (z == 0) ? 0.125f * LOG2E : 1.0f;  // fold 1/sqrt(hd) + log2e into Q
    gemm_body(A, B, C, NTOK, D_MODEL, D_MODEL,
              blockIdx.y * 128, blockIdx.x * 128, rope_mode, scale, 1);
}

__global__ __launch_bounds__(128, 2) void out_gemm_kernel(float* __restrict__ out)
{
    gemm_body(g_C, g_Wr[3], out, NTOK, D_MODEL, D_MODEL,
              blockIdx.y * 128, blockIdx.x * 128, 0, 1.0f, 0);
}

// =================================================================
// TF32 flash attention, causal. 128 threads = 4 warps, 32 q-rows/warp.
// NEW: double-buffered cp.async prefetch of K/V tiles — staging latency
// hidden behind the previous tile's mma/softmax work.
// smem floats: K0@0, K1@4352 (stride 68), V0@8704, V1@13312 (stride 72),
// Ps@17920 (stride 68). Total 26624 floats = 104 KB.
// =================================================================
#define KST 68
#define VST 72
#define PST 68
#define K0_OFF 0
#define K1_OFF (64 * KST)
#define V0_OFF (2 * 64 * KST)
#define V1_OFF (2 * 64 * KST + 64 * VST)
#define PS_OFF (2 * 64 * KST + 2 * 64 * VST)
#define ATT_SMEM4 ((PS_OFF + 128 * PST) * (int)sizeof(float))

__global__ __launch_bounds__(128, 2) void attn_tf32(
    const float* __restrict__ Q, const float* __restrict__ K,
    const float* __restrict__ V, float* __restrict__ Ctx)
{
    extern __shared__ __align__(16) float sm4[];
    float* KsB[2] = {sm4 + K0_OFF, sm4 + K1_OFF};
    float* VsB[2] = {sm4 + V0_OFF, sm4 + V1_OFF};
    float* Ps = sm4 + PS_OFF;

    const int t = threadIdx.x, warp = t >> 5, lane = t & 31;
    const int g = lane >> 2, tig = lane & 3;
    const int qb = ((int)gridDim.x - 1 - (int)blockIdx.x) * 128;  // heavy tiles first
    const int h  = blockIdx.y, b = blockIdx.z;
    const int w32 = warp * 32;

    const float* Kbase = K + (size_t)b * S_LEN * D_MODEL + h * HEAD_DIM;
    const float* Vbase = V + (size_t)b * S_LEN * D_MODEL + h * HEAD_DIM;

    // per-thread staging coords (16 threads per row-pair scheme)
    const int srow_base = t >> 4;         // 0..7
    const int sc4 = (t & 15) * 4;         // 0..60

    // prefetch K/V tile 0 before doing anything else
    {
        unsigned kb0 = (unsigned)__cvta_generic_to_shared(KsB[0]);
        unsigned vb0 = (unsigned)__cvta_generic_to_shared(VsB[0]);
#pragma unroll
        for (int i = 0; i < 8; i++) {
            int row = srow_base + i * 8;
            asm volatile("cp.async.cg.shared.global [%0], [%1], 16;"
                :: "r"(kb0 + (unsigned)(row * KST + sc4) * 4u),
                   "l"(Kbase + (size_t)row * D_MODEL + sc4));
            asm volatile("cp.async.cg.shared.global [%0], [%1], 16;"
                :: "r"(vb0 + (unsigned)(row * VST + sc4) * 4u),
                   "l"(Vbase + (size_t)row * D_MODEL + sc4));
        }
        asm volatile("cp.async.commit_group;");
    }

    // ---- stage Q (pre-rounded tf32) into Ps rows ----
    const float* Qg = Q + ((size_t)b * S_LEN + qb) * D_MODEL + h * HEAD_DIM;
#pragma unroll
    for (int i = 0; i < 16; i++) {
        int idx = t + i * 128;
        int row = idx >> 4, c4 = (idx & 15) * 4;
        *(float4*)&Ps[row * PST + c4] =
            *(const float4*)&Qg[(size_t)row * D_MODEL + c4];
    }
    __syncthreads();

    // ---- Q A-fragments for both 16-row blocks ----
    unsigned qf[2][8][4];
#pragma unroll
    for (int bb = 0; bb < 2; bb++)
#pragma unroll
        for (int kc = 0; kc < 8; kc++) {
            int rr = w32 + bb * 16 + g;
            qf[bb][kc][0] = __float_as_uint(Ps[rr * PST + kc * 8 + tig]);
            qf[bb][kc][1] = __float_as_uint(Ps[(rr + 8) * PST + kc * 8 + tig]);
            qf[bb][kc][2] = __float_as_uint(Ps[rr * PST + kc * 8 + tig + 4]);
            qf[bb][kc][3] = __float_as_uint(Ps[(rr + 8) * PST + kc * 8 + tig + 4]);
        }

    float m_[2][2], l_[2][2];
    float o[2][8][4];
#pragma unroll
    for (int bb = 0; bb < 2; bb++) {
        m_[bb][0] = -1e30f; m_[bb][1] = -1e30f;
        l_[bb][0] = 0.f;    l_[bb][1] = 0.f;
#pragma unroll
        for (int nt = 0; nt < 8; nt++)
#pragma unroll
            for (int i = 0; i < 4; i++) o[bb][nt][i] = 0.f;
    }

    const int wrow_max = qb + w32 + 31;
    const int kt_last = qb + 64;

    for (int kt = 0; kt <= kt_last; kt += 64) {
        const int buf = (kt >> 6) & 1;
        asm volatile("cp.async.wait_group 0;");
        __syncthreads();   // tile `buf` ready; all warps done reading buf^1

        // prefetch next tile into buf^1 (overlaps with compute below)
        if (kt + 64 <= kt_last) {
            unsigned kbn = (unsigned)__cvta_generic_to_shared(KsB[buf ^ 1]);
            unsigned vbn = (unsigned)__cvta_generic_to_shared(VsB[buf ^ 1]);
            const float* Kg = Kbase + (size_t)(kt + 64) * D_MODEL;
            const float* Vg = Vbase + (size_t)(kt + 64) * D_MODEL;
#pragma unroll
            for (int i = 0; i < 8; i++) {
                int row = srow_base + i * 8;
                asm volatile("cp.async.cg.shared.global [%0], [%1], 16;"
                    :: "r"(kbn + (unsigned)(row * KST + sc4) * 4u),
                       "l"(Kg + (size_t)row * D_MODEL + sc4));
                asm volatile("cp.async.cg.shared.global [%0], [%1], 16;"
                    :: "r"(vbn + (unsigned)(row * VST + sc4) * 4u),
                       "l"(Vg + (size_t)row * D_MODEL + sc4));
            }
            asm volatile("cp.async.commit_group;");
        }

        if (kt > wrow_max) continue;   // tile fully masked for this warp

        const float* Ks = KsB[buf];
        const float* Vs = VsB[buf];

        // ---- S = Q K^T for both blocks; K B-frags loaded ONCE ----
        float s[2][8][4];
#pragma unroll
        for (int nt = 0; nt < 8; nt++) {
            float c0[4] = {0.f, 0.f, 0.f, 0.f};
            float c1[4] = {0.f, 0.f, 0.f, 0.f};
#pragma unroll
            for (int kc = 0; kc < 8; kc++) {
                unsigned b0 = __float_as_uint(Ks[(nt * 8 + g) * KST + kc * 8 + tig]);
                unsigned b1 = __float_as_uint(Ks[(nt * 8 + g) * KST + kc * 8 + tig + 4]);
                mma8(c0, qf[0][kc], b0, b1);
                mma8(c1, qf[1][kc], b0, b1);
            }
#pragma unroll
            for (int i = 0; i < 4; i++) { s[0][nt][i] = c0[i]; s[1][nt][i] = c1[i]; }
        }

        // ---- causal mask + online softmax per block ----
#pragma unroll
        for (int bb = 0; bb < 2; bb++) {
            const int r0 = qb + w32 + bb * 16 + g;
            const int r1 = r0 + 8;
            if (kt + 63 > qb + w32 + bb * 16) {
#pragma unroll
                for (int nt = 0; nt < 8; nt++) {
                    int k0 = kt + nt * 8 + 2 * tig;
                    if (k0 > r0)     s[bb][nt][0] = -1e30f;
                    if (k0 + 1 > r0) s[bb][nt][1] = -1e30f;
                    if (k0 > r1)     s[bb][nt][2] = -1e30f;
                    if (k0 + 1 > r1) s[bb][nt][3] = -1e30f;
                }
            }

            float mx0 = -1e30f, mx1 = -1e30f;
#pragma unroll
            for (int nt = 0; nt < 8; nt++) {
                mx0 = fmaxf(mx0, fmaxf(s[bb][nt][0], s[bb][nt][1]));
                mx1 = fmaxf(mx1, fmaxf(s[bb][nt][2], s[bb][nt][3]));
            }
            mx0 = fmaxf(mx0, __shfl_xor_sync(0xffffffffu, mx0, 1));
            mx0 = fmaxf(mx0, __shfl_xor_sync(0xffffffffu, mx0, 2));
            mx1 = fmaxf(mx1, __shfl_xor_sync(0xffffffffu, mx1, 1));
            mx1 = fmaxf(mx1, __shfl_xor_sync(0xffffffffu, mx1, 2));

            float nm0 = fmaxf(m_[bb][0], mx0), nm1 = fmaxf(m_[bb][1], mx1);
            float a0 = exp2f(m_[bb][0] - nm0), a1 = exp2f(m_[bb][1] - nm1);
            float sum0 = 0.f, sum1 = 0.f;
#pragma unroll
            for (int nt = 0; nt < 8; nt++) {
                s[bb][nt][0] = exp2f(s[bb][nt][0] - nm0);
                s[bb][nt][1] = exp2f(s[bb][nt][1] - nm0);
                s[bb][nt][2] = exp2f(s[bb][nt][2] - nm1);
                s[bb][nt][3] = exp2f(s[bb][nt][3] - nm1);
                sum0 += s[bb][nt][0] + s[bb][nt][1];
                sum1 += s[bb][nt][2] + s[bb][nt][3];
            }
            sum0 += __shfl_xor_sync(0xffffffffu, sum0, 1);
            sum0 += __shfl_xor_sync(0xffffffffu, sum0, 2);
            sum1 += __shfl_xor_sync(0xffffffffu, sum1, 1);
            sum1 += __shfl_xor_sync(0xffffffffu, sum1, 2);

            l_[bb][0] = l_[bb][0] * a0 + sum0;
            l_[bb][1] = l_[bb][1] * a1 + sum1;
            m_[bb][0] = nm0; m_[bb][1] = nm1;
#pragma unroll
            for (int nt = 0; nt < 8; nt++) {
                o[bb][nt][0] *= a0; o[bb][nt][1] *= a0;
                o[bb][nt][2] *= a1; o[bb][nt][3] *= a1;
            }

            // P (tf32) to warp-private Ps rows
#pragma unroll
            for (int nt = 0; nt < 8; nt++) {
                *(float2*)&Ps[(w32 + bb * 16 + g) * PST + nt * 8 + 2 * tig] =
                    make_float2(f2tff(s[bb][nt][0]), f2tff(s[bb][nt][1]));
                *(float2*)&Ps[(w32 + bb * 16 + g + 8) * PST + nt * 8 + 2 * tig] =
                    make_float2(f2tff(s[bb][nt][2]), f2tff(s[bb][nt][3]));
            }
        }
        __syncwarp();

        // ---- O += P @ V; V B-frags loaded ONCE feed both blocks ----
#pragma unroll
        for (int kc = 0; kc < 8; kc++) {
            unsigned pf[2][4];
#pragma unroll
            for (int bb = 0; bb < 2; bb++) {
                int rr = w32 + bb * 16 + g;
                pf[bb][0] = __float_as_uint(Ps[rr * PST + kc * 8 + tig]);
                pf[bb][1] = __float_as_uint(Ps[(rr + 8) * PST + kc * 8 + tig]);
                pf[bb][2] = __float_as_uint(Ps[rr * PST + kc * 8 + tig + 4]);
                pf[bb][3] = __float_as_uint(Ps[(rr + 8) * PST + kc * 8 + tig + 4]);
            }
#pragma unroll
            for (int nt = 0; nt < 8; nt++) {
                unsigned b0 = __float_as_uint(Vs[(kc * 8 + tig) * VST + nt * 8 + g]);
                unsigned b1 = __float_as_uint(Vs[(kc * 8 + tig + 4) * VST + nt * 8 + g]);
                mma8(o[0][nt], pf[0], b0, b1);
                mma8(o[1][nt], pf[1], b0, b1);
            }
        }
        __syncwarp();   // Ps reads done before next iteration's stores
    }

    // ---- epilogue: normalize, round to tf32 (next GEMM input), store ----
#pragma unroll
    for (int bb = 0; bb < 2; bb++) {
        float inv0 = 1.0f / l_[bb][0], inv1 = 1.0f / l_[bb][1];
        float* Cb = Ctx + ((size_t)b * S_LEN + qb + w32 + bb * 16) * D_MODEL
                        + h * HEAD_DIM;
#pragma unroll
        for (int nt = 0; nt < 8; nt++) {
            *(float2*)&Cb[(size_t)g * D_MODEL + nt * 8 + 2 * tig] =
                make_float2(f2tff(o[bb][nt][0] * inv0), f2tff(o[bb][nt][1] * inv0));
            *(float2*)&Cb[(size_t)(g + 8) * D_MODEL + nt * 8 + 2 * tig] =
                make_float2(f2tff(o[bb][nt][2] * inv1), f2tff(o[bb][nt][3] * inv1));
        }
    }
}

// =================================================================
// Launch
// =================================================================
extern "C" void kernel_launch(void* const* d_in, const int* in_sizes, int n_in,
                              void* d_out, int out_size)
{
    const float* x  = (const float*)d_in[0];
    const float* Wq = (const float*)d_in[1];
    const float* Wk = (const float*)d_in[2];
    const float* Wv = (const float*)d_in[3];
    const float* Wo = (const float*)d_in[4];
    float* out = (float*)d_out;

    float *Q, *K, *V, *C, *Xr;
    cudaGetSymbolAddress((void**)&Q, g_Q);
    cudaGetSymbolAddress((void**)&K, g_K);
    cudaGetSymbolAddress((void**)&V, g_V);
    cudaGetSymbolAddress((void**)&C, g_C);
    cudaGetSymbolAddress((void**)&Xr, g_Xr);

    // 0: rope table
    rope_table_kernel<<<(S_LEN * 32 + 255) / 256, 256>>>();

    // 1: pre-round x + weights
    int nr4 = (NTOK * D_MODEL + 4 * D_MODEL * D_MODEL) / 4;
    preround_kernel<<<(nr4 + 255) / 256, 256>>>(x, Wq, Wk, Wv, Wo);

    // 2: fused QKV projections + RoPE epilogue (tf32-rounded outputs)
    qkv_gemm_kernel<<<dim3(D_MODEL / 128, NTOK / 128, 3), 128>>>(Xr);

    // 3: attention (4 warps x 32 rows, cp.async double-buffered K/V)
    cudaFuncSetAttribute(attn_tf32, cudaFuncAttributeMaxDynamicSharedMemorySize, ATT_SMEM4);
    attn_tf32<<<dim3(S_LEN / 128, N_HEADS, BATCH), 128, ATT_SMEM4>>>(Q, K, V, C);

    // 4: output projection
    out_gemm_kernel<<<dim3(D_MODEL / 128, NTOK / 128), 128>>>(out);
}

// round 11
// speedup vs baseline: 1.2097x; 1.2097x over previous
#include <cuda_runtime.h>
#include <math.h>
#include <stdint.h>

#define S_LEN    2048
#define D_MODEL  1024
#define N_HEADS  16
#define HEAD_DIM 64
#define BATCH    2
#define NTOK     (BATCH * S_LEN)   // 4096

// -------- scratch (device globals: no allocations allowed) --------
__device__ float g_Q[NTOK * D_MODEL];
__device__ float g_K[NTOK * D_MODEL];
__device__ float g_V[NTOK * D_MODEL];
__device__ float g_C[NTOK * D_MODEL];
__device__ float g_Xp[NTOK * D_MODEL];            // x, tf32-rounded, A-frag order
__device__ float g_Wp[4][D_MODEL * D_MODEL];      // weights, tf32-rounded, B-frag order
__device__ float g_cos[S_LEN * 32];
__device__ float g_sin[S_LEN * 32];

#define LOG2E 1.4426950408889634f

__device__ __forceinline__ unsigned f2tf(float x) {
    unsigned u;
    asm("cvt.rna.tf32.f32 %0, %1;" : "=r"(u) : "f"(x));
    return u;
}
__device__ __forceinline__ float f2tff(float x) { return __uint_as_float(f2tf(x)); }

__device__ __forceinline__ void mma8(float c[4], const unsigned a[4],
                                     unsigned b0, unsigned b1) {
    asm volatile(
        "mma.sync.aligned.m16n8k8.row.col.f32.tf32.tf32.f32 "
        "{%0,%1,%2,%3},{%4,%5,%6,%7},{%8,%9},{%0,%1,%2,%3};"
        : "+f"(c[0]), "+f"(c[1]), "+f"(c[2]), "+f"(c[3])
        : "r"(a[0]), "r"(a[1]), "r"(a[2]), "r"(a[3]), "r"(b0), "r"(b1));
}

// =================================================================
// Preround + permute:
//  A-frag layout (x): ((((m_tile*64+stage)*2+ks)*8+mt)*32+lane)*4 + j
//    lane = g*4+tig, j = r8 + 2*e4   (r8 = (mrow>>3)&1, e4 = (k>>2)&1)
//  B-frag layout (W): ((((n_tile*64+stage)*2+ks)*16+nt)*32+lane)*2 + j
//    lane = g*4+tig, j = (k>>2)&1    (nt = nrow>>3, g = nrow&7)
// =================================================================
__global__ void preround_permute_kernel(const float* __restrict__ x,
                                        const float* __restrict__ Wq,
                                        const float* __restrict__ Wk,
                                        const float* __restrict__ Wv,
                                        const float* __restrict__ Wo)
{
    const int NXq = NTOK * (D_MODEL / 4);        // 1M quads
    const int NWq = D_MODEL * (D_MODEL / 4);     // 256K quads per W
    int idx = blockIdx.x * blockDim.x + threadIdx.x;
    if (idx < NXq) {
        int m = idx >> 8, k4 = idx & 255;
        float4 v = *(const float4*)&x[(size_t)m * D_MODEL + k4 * 4];
        int m_tile = m >> 7, mrow = m & 127;
        int mt = mrow >> 4, r8 = (mrow >> 3) & 1, g = mrow & 7;
        int stage = k4 >> 2, ks = (k4 >> 1) & 1, e4 = k4 & 1;
        int j = r8 + 2 * e4;
        float* base = g_Xp + ((((size_t)m_tile * 64 + stage) * 2 + ks) * 8 + mt) * 128;
        base[(g * 4 + 0) * 4 + j] = f2tff(v.x);
        base[(g * 4 + 1) * 4 + j] = f2tff(v.y);
        base[(g * 4 + 2) * 4 + j] = f2tff(v.z);
        base[(g * 4 + 3) * 4 + j] = f2tff(v.w);
    } else if (idx < NXq + 4 * NWq) {
        int r = idx - NXq;
        int w = r / NWq; r -= w * NWq;
        int n = r >> 8, k4 = r & 255;
        const float* ws[4] = {Wq, Wk, Wv, Wo};
        float4 v = *(const float4*)&ws[w][(size_t)n * D_MODEL + k4 * 4];
        int n_tile = n >> 7, nrow = n & 127;
        int nt = nrow >> 3, g = nrow & 7;
        int stage = k4 >> 2, ks = (k4 >> 1) & 1, j = k4 & 1;
        float* base = g_Wp[w] + ((((size_t)n_tile * 64 + stage) * 2 + ks) * 16 + nt) * 64;
        base[(g * 4 + 0) * 2 + j] = f2tff(v.x);
        base[(g * 4 + 1) * 2 + j] = f2tff(v.y);
        base[(g * 4 + 2) * 2 + j] = f2tff(v.z);
        base[(g * 4 + 3) * 2 + j] = f2tff(v.w);
    }
}

// =================================================================
// RoPE table (fp32 angle matching jnp, fp64 sincos)
// =================================================================
__global__ void rope_table_kernel()
{
    int i = blockIdx.x * blockDim.x + threadIdx.x;
    if (i >= S_LEN * 32) return;
    int pos = i >> 5;
    int f   = i & 31;
    float e    = (float)(2 * f) / 64.0f;
    float pw   = powf(10000.0f, e);
    float invf = 1.0f / pw;
    float angf = (float)pos * invf;
    double s, c;
    sincos((double)angf, &s, &c);
    g_cos[i] = (float)c;
    g_sin[i] = (float)s;
}

// =================================================================
// QKV GEMM: both operands pre-permuted to fragment order.
// 128x128x16 CTA tile, 128 threads = 4 warps (2x2), 64x64 warp tile.
// Mainloop per ks: 4x LDS.128 (A) + 8x LDS.64 (B) + 32 mma.
// 3-stage cp.async (2048-float contiguous chunks), one sync per iter.
// =================================================================
__global__ __launch_bounds__(128, 2) void qkv_gemm_kernel()
{
    __shared__ __align__(16) float As[3][2048];
    __shared__ __align__(16) float Bs[3][2048];

    const int z = blockIdx.z;
    const int t = threadIdx.x, warp = t >> 5, lane = t & 31;
    const int g = lane >> 2, tig = lane & 3;
    const int mtb = (warp >> 1) * 4;       // mt_global base
    const int ntb = (warp & 1) * 8;        // nt_global base
    const int mb = blockIdx.y * 128, nb = blockIdx.x * 128;

    const float* Ag = g_Xp + (size_t)blockIdx.y * 64 * 2048;
    const float* Bg = g_Wp[z] + (size_t)blockIdx.x * 64 * 2048;

    float* outs[3] = {g_Q, g_K, g_V};
    float* C = outs[z];
    const int rope_mode = (z < 2) ? 1 : 0;
    const float scale = (z == 0) ? 0.125f * LOG2E : 1.0f;

    float acc[4][8][4];
#pragma unroll
    for (int mt = 0; mt < 4; mt++)
#pragma unroll
        for (int nt = 0; nt < 8; nt++)
#pragma unroll
            for (int i = 0; i < 4; i++) acc[mt][nt][i] = 0.f;

#define LOADP(buf, s)                                                              \
    do {                                                                           \
        _Pragma("unroll")                                                          \
        for (int ii = 0; ii < 4; ii++) {                                           \
            int q = t + ii * 128;                                                  \
            unsigned da = (unsigned)__cvta_generic_to_shared(&As[buf][q * 4]);     \
            asm volatile("cp.async.cg.shared.global [%0], [%1], 16;"               \
                         :: "r"(da), "l"(Ag + (size_t)(s) * 2048 + q * 4));        \
            unsigned db = (unsigned)__cvta_generic_to_shared(&Bs[buf][q * 4]);     \
            asm volatile("cp.async.cg.shared.global [%0], [%1], 16;"               \
                         :: "r"(db), "l"(Bg + (size_t)(s) * 2048 + q * 4));        \
        }                                                                          \
        asm volatile("cp.async.commit_group;");                                    \
    } while (0)

    LOADP(0, 0);
    LOADP(1, 1);

    for (int i = 0; i < 64; i++) {
        asm volatile("cp.async.wait_group 1;");
        __syncthreads();
        if (i + 2 < 64) LOADP((i + 2) % 3, i + 2);
        const float* Ab = As[i % 3];
        const float* Bb = Bs[i % 3];

#pragma unroll
        for (int ks = 0; ks < 2; ks++) {
            unsigned af[4][4], bf[8][2];
#pragma unroll
            for (int mt = 0; mt < 4; mt++) {
                float4 a4 = *(const float4*)&Ab[((ks * 8 + mtb + mt) * 32 + lane) * 4];
                af[mt][0] = __float_as_uint(a4.x);
                af[mt][1] = __float_as_uint(a4.y);
                af[mt][2] = __float_as_uint(a4.z);
                af[mt][3] = __float_as_uint(a4.w);
            }
#pragma unroll
            for (int nt = 0; nt < 8; nt++) {
                float2 b2 = *(const float2*)&Bb[((ks * 16 + ntb + nt) * 32 + lane) * 2];
                bf[nt][0] = __float_as_uint(b2.x);
                bf[nt][1] = __float_as_uint(b2.y);
            }
#pragma unroll
            for (int mt = 0; mt < 4; mt++)
#pragma unroll
                for (int nt = 0; nt < 8; nt++)
                    mma8(acc[mt][nt], af[mt], bf[nt][0], bf[nt][1]);
        }
    }

    // ---- epilogue: fused RoPE (Q,K) + tf32 rounding ----
#pragma unroll
    for (int mt = 0; mt < 4; mt++) {
#pragma unroll
        for (int nt = 0; nt < 8; nt++) {
            int row = mb + (warp >> 1) * 64 + mt * 16 + g;
            int col = nb + (warp & 1) * 64 + nt * 8 + 2 * tig;
            float v0 = acc[mt][nt][0], v1 = acc[mt][nt][1];
            float v2 = acc[mt][nt][2], v3 = acc[mt][nt][3];
            if (rope_mode) {
                int fi = (col & 63) >> 1;
                int p0 = row & (S_LEN - 1);
                int p1 = (row + 8) & (S_LEN - 1);
                float c0 = g_cos[p0 * 32 + fi], s0 = g_sin[p0 * 32 + fi];
                float c1 = g_cos[p1 * 32 + fi], s1 = g_sin[p1 * 32 + fi];
                float r0 = v0 * c0 - v1 * s0, r1 = v0 * s0 + v1 * c0;
                float r2 = v2 * c1 - v3 * s1, r3 = v2 * s1 + v3 * c1;
                v0 = r0 * scale; v1 = r1 * scale;
                v2 = r2 * scale; v3 = r3 * scale;
            }
            v0 = f2tff(v0); v1 = f2tff(v1);
            v2 = f2tff(v2); v3 = f2tff(v3);
            *(float2*)&C[(size_t)row * D_MODEL + col] = make_float2(v0, v1);
            *(float2*)&C[(size_t)(row + 8) * D_MODEL + col] = make_float2(v2, v3);
        }
    }
}

// =================================================================
// Output GEMM: A = g_C (row-major, from attention), B = Wo (permuted).
// A staged old-style (AST=20 pad), B staged fragment-order.
// =================================================================
#define AST 20

__global__ __launch_bounds__(128, 2) void out_gemm_kernel(float* __restrict__ out)
{
    __shared__ __align__(16) float As[3][128 * AST];
    __shared__ __align__(16) float Bs[3][2048];

    const int t = threadIdx.x, warp = t >> 5, lane = t & 31;
    const int g = lane >> 2, tig = lane & 3;
    const int wm = (warp >> 1) * 64;
    const int ntb = (warp & 1) * 8;
    const int mb = blockIdx.y * 128, nb = blockIdx.x * 128;

    const float* A = g_C;
    const float* Bg = g_Wp[3] + (size_t)blockIdx.x * 64 * 2048;

    float acc[4][8][4];
#pragma unroll
    for (int mt = 0; mt < 4; mt++)
#pragma unroll
        for (int nt = 0; nt < 8; nt++)
#pragma unroll
            for (int i = 0; i < 4; i++) acc[mt][nt][i] = 0.f;

    const int lrow = t >> 2, lcol = (t & 3) * 4;

#define LOADO(buf, s)                                                              \
    do {                                                                           \
        _Pragma("unroll")                                                          \
        for (int rr = 0; rr < 4; rr++) {                                           \
            int row = lrow + rr * 32;                                              \
            unsigned da = (unsigned)__cvta_generic_to_shared(                      \
                &As[buf][row * AST + lcol]);                                       \
            asm volatile("cp.async.cg.shared.global [%0], [%1], 16;"               \
                :: "r"(da), "l"(A + (size_t)(mb + row) * D_MODEL + (s) * 16 + lcol)); \
            int q = t + rr * 128;                                                  \
            unsigned db = (unsigned)__cvta_generic_to_shared(&Bs[buf][q * 4]);     \
            asm volatile("cp.async.cg.shared.global [%0], [%1], 16;"               \
                :: "r"(db), "l"(Bg + (size_t)(s) * 2048 + q * 4));                 \
        }                                                                          \
        asm volatile("cp.async.commit_group;");                                    \
    } while (0)

    LOADO(0, 0);
    LOADO(1, 1);

    for (int i = 0; i < 64; i++) {
        asm volatile("cp.async.wait_group 1;");
        __syncthreads();
        if (i + 2 < 64) LOADO((i + 2) % 3, i + 2);
        const float* Ab = As[i % 3];
        const float* Bb = Bs[i % 3];

#pragma unroll
        for (int ks = 0; ks < 2; ks++) {
            const int kb = ks * 8;
            unsigned af[4][4], bf[8][2];
#pragma unroll
            for (int mt = 0; mt < 4; mt++) {
                int r0 = wm + mt * 16 + g;
                af[mt][0] = __float_as_uint(Ab[r0 * AST + kb + tig]);
                af[mt][1] = __float_as_uint(Ab[(r0 + 8) * AST + kb + tig]);
                af[mt][2] = __float_as_uint(Ab[r0 * AST + kb + tig + 4]);
                af[mt][3] = __float_as_uint(Ab[(r0 + 8) * AST + kb + tig + 4]);
            }
#pragma unroll
            for (int nt = 0; nt < 8; nt++) {
                float2 b2 = *(const float2*)&Bb[((ks * 16 + ntb + nt) * 32 + lane) * 2];
                bf[nt][0] = __float_as_uint(b2.x);
                bf[nt][1] = __float_as_uint(b2.y);
            }
#pragma unroll
            for (int mt = 0; mt < 4; mt++)
#pragma unroll
                for (int nt = 0; nt < 8; nt++)
                    mma8(acc[mt][nt], af[mt], bf[nt][0], bf[nt][1]);
        }
    }

#pragma unroll
    for (int mt = 0; mt < 4; mt++) {
#pragma unroll
        for (int nt = 0; nt < 8; nt++) {
            int row = mb + wm + mt * 16 + g;
            int col = nb + (warp & 1) * 64 + nt * 8 + 2 * tig;
            *(float2*)&out[(size_t)row * D_MODEL + col] =
                make_float2(acc[mt][nt][0], acc[mt][nt][1]);
            *(float2*)&out[(size_t)(row + 8) * D_MODEL + col] =
                make_float2(acc[mt][nt][2], acc[mt][nt][3]);
        }
    }
}

// =================================================================
// TF32 flash attention, causal — R8-exact (176us): 128 threads = 4 warps,
// 32 q-rows/warp, single-buffer LDG->STS staging.
// =================================================================
#define KST 68
#define VST 72
#define PST 68
#define KS_OFF 0
#define VS_OFF (64 * KST)
#define PS_OFF (64 * KST + 64 * VST)
#define ATT_SMEM3 ((64 * KST + 64 * VST + 128 * PST) * (int)sizeof(float))

__global__ __launch_bounds__(128, 2) void attn_tf32(
    const float* __restrict__ Q, const float* __restrict__ K,
    const float* __restrict__ V, float* __restrict__ Ctx)
{
    extern __shared__ __align__(16) float sm3[];
    float* Ks = sm3 + KS_OFF;
    float* Vs = sm3 + VS_OFF;
    float* Ps = sm3 + PS_OFF;

    const int t = threadIdx.x, warp = t >> 5, lane = t & 31;
    const int g = lane >> 2, tig = lane & 3;
    const int qb = ((int)gridDim.x - 1 - (int)blockIdx.x) * 128;  // heavy tiles first
    const int h  = blockIdx.y, b = blockIdx.z;
    const int w32 = warp * 32;

    const float* Qg = Q + ((size_t)b * S_LEN + qb) * D_MODEL + h * HEAD_DIM;

#pragma unroll
    for (int i = 0; i < 16; i++) {
        int idx = t + i * 128;
        int row = idx >> 4, c4 = (idx & 15) * 4;
        *(float4*)&Ps[row * PST + c4] =
            *(const float4*)&Qg[(size_t)row * D_MODEL + c4];
    }
    __syncthreads();

    unsigned qf[2][8][4];
#pragma unroll
    for (int bb = 0; bb < 2; bb++)
#pragma unroll
        for (int kc = 0; kc < 8; kc++) {
            int rr = w32 + bb * 16 + g;
            qf[bb][kc][0] = __float_as_uint(Ps[rr * PST + kc * 8 + tig]);
            qf[bb][kc][1] = __float_as_uint(Ps[(rr + 8) * PST + kc * 8 + tig]);
            qf[bb][kc][2] = __float_as_uint(Ps[rr * PST + kc * 8 + tig + 4]);
            qf[bb][kc][3] = __float_as_uint(Ps[(rr + 8) * PST + kc * 8 + tig + 4]);
        }

    float m_[2][2], l_[2][2];
    float o[2][8][4];
#pragma unroll
    for (int bb = 0; bb < 2; bb++) {
        m_[bb][0] = -1e30f; m_[bb][1] = -1e30f;
        l_[bb][0] = 0.f;    l_[bb][1] = 0.f;
#pragma unroll
        for (int nt = 0; nt < 8; nt++)
#pragma unroll
            for (int i = 0; i < 4; i++) o[bb][nt][i] = 0.f;
    }

    const int wrow_max = qb + w32 + 31;

    for (int kt = 0; kt <= qb + 64; kt += 64) {
        __syncthreads();
        const float* Kg = K + ((size_t)b * S_LEN + kt) * D_MODEL + h * HEAD_DIM;
        const float* Vg = V + ((size_t)b * S_LEN + kt) * D_MODEL + h * HEAD_DIM;
#pragma unroll
        for (int i = 0; i < 8; i++) {
            int idx = t + i * 128;
            int row = idx >> 4, c4 = (idx & 15) * 4;
            *(float4*)&Ks[row * KST + c4] =
                *(const float4*)&Kg[(size_t)row * D_MODEL + c4];
            *(float4*)&Vs[row * VST + c4] =
                *(const float4*)&Vg[(size_t)row * D_MODEL + c4];
        }
        __syncthreads();

        if (kt > wrow_max) continue;

        float s[2][8][4];
#pragma unroll
        for (int nt = 0; nt < 8; nt++) {
            float c0[4] = {0.f, 0.f, 0.f, 0.f};
            float c1[4] = {0.f, 0.f, 0.f, 0.f};
#pragma unroll
            for (int kc = 0; kc < 8; kc++) {
                unsigned b0 = __float_as_uint(Ks[(nt * 8 + g) * KST + kc * 8 + tig]);
                unsigned b1 = __float_as_uint(Ks[(nt * 8 + g) * KST + kc * 8 + tig + 4]);
                mma8(c0, qf[0][kc], b0, b1);
                mma8(c1, qf[1][kc], b0, b1);
            }
#pragma unroll
            for (int i = 0; i < 4; i++) { s[0][nt][i] = c0[i]; s[1][nt][i] = c1[i]; }
        }

#pragma unroll
        for (int bb = 0; bb < 2; bb++) {
            const int r0 = qb + w32 + bb * 16 + g;
            const int r1 = r0 + 8;
            if (kt + 63 > qb + w32 + bb * 16) {
#pragma unroll
                for (int nt = 0; nt < 8; nt++) {
                    int k0 = kt + nt * 8 + 2 * tig;
                    if (k0 > r0)     s[bb][nt][0] = -1e30f;
                    if (k0 + 1 > r0) s[bb][nt][1] = -1e30f;
                    if (k0 > r1)     s[bb][nt][2] = -1e30f;
                    if (k0 + 1 > r1) s[bb][nt][3] = -1e30f;
                }
            }

            float mx0 = -1e30f, mx1 = -1e30f;
#pragma unroll
            for (int nt = 0; nt < 8; nt++) {
                mx0 = fmaxf(mx0, fmaxf(s[bb][nt][0], s[bb][nt][1]));
                mx1 = fmaxf(mx1, fmaxf(s[bb][nt][2], s[bb][nt][3]));
            }
            mx0 = fmaxf(mx0, __shfl_xor_sync(0xffffffffu, mx0, 1));
            mx0 = fmaxf(mx0, __shfl_xor_sync(0xffffffffu, mx0, 2));
            mx1 = fmaxf(mx1, __shfl_xor_sync(0xffffffffu, mx1, 1));
            mx1 = fmaxf(mx1, __shfl_xor_sync(0xffffffffu, mx1, 2));

            float nm0 = fmaxf(m_[bb][0], mx0), nm1 = fmaxf(m_[bb][1], mx1);
            float a0 = exp2f(m_[bb][0] - nm0), a1 = exp2f(m_[bb][1] - nm1);
            float sum0 = 0.f, sum1 = 0.f;
#pragma unroll
            for (int nt = 0; nt < 8; nt++) {
                s[bb][nt][0] = exp2f(s[bb][nt][0] - nm0);
                s[bb][nt][1] = exp2f(s[bb][nt][1] - nm0);
                s[bb][nt][2] = exp2f(s[bb][nt][2] - nm1);
                s[bb][nt][3] = exp2f(s[bb][nt][3] - nm1);
                sum0 += s[bb][nt][0] + s[bb][nt][1];
                sum1 += s[bb][nt][2] + s[bb][nt][3];
            }
            sum0 += __shfl_xor_sync(0xffffffffu, sum0, 1);
            sum0 += __shfl_xor_sync(0xffffffffu, sum0, 2);
            sum1 += __shfl_xor_sync(0xffffffffu, sum1, 1);
            sum1 += __shfl_xor_sync(0xffffffffu, sum1, 2);

            l_[bb][0] = l_[bb][0] * a0 + sum0;
            l_[bb][1] = l_[bb][1] * a1 + sum1;
            m_[bb][0] = nm0; m_[bb][1] = nm1;
#pragma unroll
            for (int nt = 0; nt < 8; nt++) {
                o[bb][nt][0] *= a0; o[bb][nt][1] *= a0;
                o[bb][nt][2] *= a1; o[bb][nt][3] *= a1;
            }

#pragma unroll
            for (int nt = 0; nt < 8; nt++) {
                *(float2*)&Ps[(w32 + bb * 16 + g) * PST + nt * 8 + 2 * tig] =
                    make_float2(f2tff(s[bb][nt][0]), f2tff(s[bb][nt][1]));
                *(float2*)&Ps[(w32 + bb * 16 + g + 8) * PST + nt * 8 + 2 * tig] =
                    make_float2(f2tff(s[bb][nt][2]), f2tff(s[bb][nt][3]));
            }
        }
        __syncwarp();

#pragma unroll
        for (int kc = 0; kc < 8; kc++) {
            unsigned pf[2][4];
#pragma unroll
            for (int bb = 0; bb < 2; bb++) {
                int rr = w32 + bb * 16 + g;
                pf[bb][0] = __float_as_uint(Ps[rr * PST + kc * 8 + tig]);
                pf[bb][1] = __float_as_uint(Ps[(rr + 8) * PST + kc * 8 + tig]);
                pf[bb][2] = __float_as_uint(Ps[rr * PST + kc * 8 + tig + 4]);
                pf[bb][3] = __float_as_uint(Ps[(rr + 8) * PST + kc * 8 + tig + 4]);
            }
#pragma unroll
            for (int nt = 0; nt < 8; nt++) {
                unsigned b0 = __float_as_uint(Vs[(kc * 8 + tig) * VST + nt * 8 + g]);
                unsigned b1 = __float_as_uint(Vs[(kc * 8 + tig + 4) * VST + nt * 8 + g]);
                mma8(o[0][nt], pf[0], b0, b1);
                mma8(o[1][nt], pf[1], b0, b1);
            }
        }
        __syncwarp();
    }

#pragma unroll
    for (int bb = 0; bb < 2; bb++) {
        float inv0 = 1.0f / l_[bb][0], inv1 = 1.0f / l_[bb][1];
        float* Cb = Ctx + ((size_t)b * S_LEN + qb + w32 + bb * 16) * D_MODEL
                        + h * HEAD_DIM;
#pragma unroll
        for (int nt = 0; nt < 8; nt++) {
            *(float2*)&Cb[(size_t)g * D_MODEL + nt * 8 + 2 * tig] =
                make_float2(f2tff(o[bb][nt][0] * inv0), f2tff(o[bb][nt][1] * inv0));
            *(float2*)&Cb[(size_t)(g + 8) * D_MODEL + nt * 8 + 2 * tig] =
                make_float2(f2tff(o[bb][nt][2] * inv1), f2tff(o[bb][nt][3] * inv1));
        }
    }
}

// =================================================================
// Launch
// =================================================================
extern "C" void kernel_launch(void* const* d_in, const int* in_sizes, int n_in,
                              void* d_out, int out_size)
{
    const float* x  = (const float*)d_in[0];
    const float* Wq = (const float*)d_in[1];
    const float* Wk = (const float*)d_in[2];
    const float* Wv = (const float*)d_in[3];
    const float* Wo = (const float*)d_in[4];
    float* out = (float*)d_out;

    float *Q, *K, *V, *C;
    cudaGetSymbolAddress((void**)&Q, g_Q);
    cudaGetSymbolAddress((void**)&K, g_K);
    cudaGetSymbolAddress((void**)&V, g_V);
    cudaGetSymbolAddress((void**)&C, g_C);

    // 0: rope table
    rope_table_kernel<<<(S_LEN * 32 + 255) / 256, 256>>>();

    // 1: pre-round + permute x and weights into fragment order
    int nthreads = NTOK * (D_MODEL / 4) + 4 * D_MODEL * (D_MODEL / 4);
    preround_permute_kernel<<<(nthreads + 255) / 256, 256>>>(x, Wq, Wk, Wv, Wo);

    // 2: fused QKV projections (frag-order operands) + RoPE epilogue
    qkv_gemm_kernel<<<dim3(D_MODEL / 128, NTOK / 128, 3), 128>>>();

    // 3: attention (R8-exact)
    cudaFuncSetAttribute(attn_tf32, cudaFuncAttributeMaxDynamicSharedMemorySize, ATT_SMEM3);
    attn_tf32<<<dim3(S_LEN / 128, N_HEADS, BATCH), 128, ATT_SMEM3>>>(Q, K, V, C);

    // 4: output projection (frag-order B)
    out_gemm_kernel<<<dim3(D_MODEL / 128, NTOK / 128), 128>>>(out);
}